// round 6
// baseline (speedup 1.0000x reference)
#include <cuda_runtime.h>
#include <cstdint>

// Problem constants (match reference)
#define NN      100000
#define EE      3200000
#define GAMMA   0.1f

#define EDGE_THREADS  EE                        // 3,200,000 (1 edge each)
#define DAMP_THREADS  ((NN + 1) / 2)            // 50,000 (2 nodes each)
#define TOTAL_THREADS (EDGE_THREADS + DAMP_THREADS)

__device__ __forceinline__ void red_add_v2(float* addr, float a, float b) {
    asm volatile("red.global.add.v2.f32 [%0], {%1, %2};"
                 :: "l"(addr), "f"(a), "f"(b) : "memory");
}

__device__ __forceinline__ int ldcs_int(const int* p) {
    int r;
    asm volatile("ld.global.cs.s32 %0, [%1];" : "=r"(r) : "l"(p));
    return r;
}

// Flat one-edge-per-thread kernel over zero-initialized out:
//   threads [0, EE):           1 edge  -> red.add message into out[dst]
//   threads [EE, +DAMP):       2 nodes -> red.add(-gamma*v)
// All contributions are atomic adds; no ordering needed.
__global__ void __launch_bounds__(256) fused_edge_damp_kernel(
        const float* __restrict__ x,
        const float* __restrict__ v,
        const int*   __restrict__ src,
        const int*   __restrict__ dst,
        float* __restrict__ out) {
    int t = blockIdx.x * blockDim.x + threadIdx.x;

    if (t < EDGE_THREADS) {
        const float2* __restrict__ x2 = reinterpret_cast<const float2*>(x);

        int s = ldcs_int(src + t);
        int d = ldcs_int(dst + t);

        float2 xs = __ldg(&x2[s]);
        float2 xd = __ldg(&x2[d]);

        float drx = xd.x - xs.x;
        float dry = xd.y - xs.y;
        float d2  = fmaf(drx, drx, dry * dry);
        // f = -C*P*(ab - R_C)/ab = 2*rsqrt(d2) - 2 ; zero for d2==0
        float f = (d2 > 0.0f) ? fmaf(2.0f, rsqrtf(d2), -2.0f) : 0.0f;
        red_add_v2(out + 2 * d, f * drx, f * dry);
    } else {
        int i2 = (t - EDGE_THREADS) * 2;
#pragma unroll
        for (int k = 0; k < 2; k++) {
            int i = i2 + k;
            if (i < NN) {
                float2 vv = __ldg(&reinterpret_cast<const float2*>(v)[i]);
                red_add_v2(out + 2 * i, -GAMMA * vv.x, -GAMMA * vv.y);
            }
        }
    }
}

extern "C" void kernel_launch(void* const* d_in, const int* in_sizes, int n_in,
                              void* d_out, int out_size) {
    const float* x   = (const float*)d_in[0];
    const float* v   = (const float*)d_in[1];
    const int*   src = (const int*)d_in[2];
    const int*   dst = (const int*)d_in[3];
    float* out = (float*)d_out;

    // Zero the accumulator (graph-capturable memset node).
    cudaMemsetAsync(out, 0, (size_t)out_size * sizeof(float), 0);

    int threads = 256;
    int blocks = (TOTAL_THREADS + threads - 1) / threads;  // 12696
    fused_edge_damp_kernel<<<blocks, threads>>>(x, v, src, dst, out);
}